// round 8
// baseline (speedup 1.0000x reference)
#include <cuda_runtime.h>
#include <cuda_bf16.h>
#include <cstdint>
#include <cstddef>

// out = x @ (2048 * Wv @ Wo) + (2048 * bv @ Wo + bo)
// (reference's einsum 'bvhd,bhqk->bvhd' sums softmax over q,k -> factor L=2048)
// fp32 emulated as split-bf16: A@B ~= Ah@Bh + Al@Bh + Ah@Bl, fp32 accum,
// via mma.sync.m16n8k16 (arch-neutral PTX; tcgen05 unavailable: harness targets sm_103 non-'a').
//
// weffT[n][i] = sum_c Wo[c][n] * Wv[i][c]:  A = WoT (transposed), B = Wv (PLAIN).
// R6: 512 threads / 16 warps per CTA (4 warps/SMSP), warp tile 32x32.

// ---------------------------------------------------------------------------
__device__ __forceinline__ uint32_t smem_u32(const void* p) {
    uint32_t a;
    asm("{ .reg .u64 t; cvta.to.shared.u64 t, %1; cvt.u32.u64 %0, t; }" : "=r"(a) : "l"(p));
    return a;
}
__device__ __forceinline__ void cp_async16(uint32_t saddr, const void* gaddr) {
    asm volatile("cp.async.cg.shared.global [%0], [%1], 16;" :: "r"(saddr), "l"(gaddr));
}
#define CP_COMMIT() asm volatile("cp.async.commit_group;" ::: "memory")
template <int N> __device__ __forceinline__ void cp_wait() {
    asm volatile("cp.async.wait_group %0;" :: "n"(N) : "memory");
}
__device__ __forceinline__ void ldsm_x4(uint32_t* r, uint32_t addr) {
    asm volatile("ldmatrix.sync.aligned.m8n8.x4.shared.b16 {%0,%1,%2,%3}, [%4];"
        : "=r"(r[0]), "=r"(r[1]), "=r"(r[2]), "=r"(r[3]) : "r"(addr));
}
__device__ __forceinline__ void mma16816(float* c, const uint32_t* a, const uint32_t* b) {
    asm volatile(
        "mma.sync.aligned.m16n8k16.row.col.f32.bf16.bf16.f32 "
        "{%0,%1,%2,%3}, {%4,%5,%6,%7}, {%8,%9}, {%0,%1,%2,%3};"
        : "+f"(c[0]), "+f"(c[1]), "+f"(c[2]), "+f"(c[3])
        : "r"(a[0]), "r"(a[1]), "r"(a[2]), "r"(a[3]), "r"(b[0]), "r"(b[1]));
}

// ---------------------------------------------------------------------------
// Scratch (__device__ globals; no allocation allowed)
// ---------------------------------------------------------------------------
__device__ __nv_bfloat16 g_x_hi[8192 * 1024];
__device__ __nv_bfloat16 g_x_lo[8192 * 1024];
__device__ __nv_bfloat16 g_wv_hi[1024 * 1024];
__device__ __nv_bfloat16 g_wv_lo[1024 * 1024];
__device__ __nv_bfloat16 g_woT_hi[1024 * 1024];
__device__ __nv_bfloat16 g_woT_lo[1024 * 1024];
__device__ __nv_bfloat16 g_wT_hi[1024 * 1024];
__device__ __nv_bfloat16 g_wT_lo[1024 * 1024];
__device__ float g_beff[1024];

// ---------------------------------------------------------------------------
// Conversion kernels
// ---------------------------------------------------------------------------
__global__ void split_kernel(const float* __restrict__ in,
                             __nv_bfloat16* __restrict__ hi,
                             __nv_bfloat16* __restrict__ lo, int n4) {
    int i = blockIdx.x * blockDim.x + threadIdx.x;
    if (i >= n4) return;
    float4 v = reinterpret_cast<const float4*>(in)[i];
    __nv_bfloat16 h0 = __float2bfloat16(v.x), h1 = __float2bfloat16(v.y);
    __nv_bfloat16 h2 = __float2bfloat16(v.z), h3 = __float2bfloat16(v.w);
    __nv_bfloat162* hp = reinterpret_cast<__nv_bfloat162*>(hi);
    __nv_bfloat162* lp = reinterpret_cast<__nv_bfloat162*>(lo);
    hp[2 * i]     = __nv_bfloat162(h0, h1);
    hp[2 * i + 1] = __nv_bfloat162(h2, h3);
    lp[2 * i]     = __nv_bfloat162(__float2bfloat16(v.x - __bfloat162float(h0)),
                                   __float2bfloat16(v.y - __bfloat162float(h1)));
    lp[2 * i + 1] = __nv_bfloat162(__float2bfloat16(v.z - __bfloat162float(h2)),
                                   __float2bfloat16(v.w - __bfloat162float(h3)));
}

// Transposing split: out[n][c] = split(in[c][n]); 1024x1024
__global__ void splitT_kernel(const float* __restrict__ in,
                              __nv_bfloat16* __restrict__ hiT,
                              __nv_bfloat16* __restrict__ loT) {
    __shared__ float t[32][33];
    const int bx = blockIdx.x * 32, by = blockIdx.y * 32;
    const int tx = threadIdx.x, ty = threadIdx.y;  // 32 x 8
    #pragma unroll
    for (int i = 0; i < 32; i += 8)
        t[ty + i][tx] = in[(size_t)(by + ty + i) * 1024 + bx + tx];
    __syncthreads();
    #pragma unroll
    for (int i = 0; i < 32; i += 8) {
        float v = t[tx][ty + i];
        __nv_bfloat16 h = __float2bfloat16(v);
        size_t o = (size_t)(bx + ty + i) * 1024 + by + tx;
        hiT[o] = h;
        loT[o] = __float2bfloat16(v - __bfloat162float(h));
    }
}

// beff[j] = 2048 * sum_k bv[k]*Wo[k][j] + bo[j]; one block per j
__global__ void beff_kernel(const float* __restrict__ bv, const float* __restrict__ Wo,
                            const float* __restrict__ bo, float* __restrict__ beff) {
    __shared__ float red[256];
    const int j = blockIdx.x;
    float s = 0.0f;
    for (int k = threadIdx.x; k < 1024; k += 256)
        s += bv[k] * Wo[(size_t)k * 1024 + j];
    red[threadIdx.x] = s;
    __syncthreads();
    for (int st = 128; st > 0; st >>= 1) {
        if (threadIdx.x < st) red[threadIdx.x] += red[threadIdx.x + st];
        __syncthreads();
    }
    if (threadIdx.x == 0) beff[j] = 2048.0f * red[0] + bo[j];
}

// ---------------------------------------------------------------------------
// Split-bf16 GEMM via mma.sync: D[m][n] = sum_k A[m][k]*B[n][k]
//   A: [M x 1024] K-major (hi/lo), B: [N x 1024] K-major (hi/lo)
// MODE 0: out_f = D + bias;  MODE 1: (out_hi,out_lo) = split(D * scale)
// CTA tile 128x128, BK=32, 512 thr (16 warps, 4x4), warp tile 32x32,
// double-buffered cp.async, 80B-pitch smem (ldmatrix conflict-free).
// ---------------------------------------------------------------------------
#define PITCH 80
#define TILE_B (128 * PITCH)       // 10240 bytes: one 128x32 bf16 tile
#define STAGE_B (4 * TILE_B)       // AH, AL, BH, BL
#define SMEM_B (2 * STAGE_B)       // 81920

__device__ __forceinline__ void load_tile(uint32_t s, const __nv_bfloat16* g,
                                          int row0, int k0, int tid) {
    // 512 chunks of 16B, 512 threads -> exactly 1 each
    const int r = tid >> 2, c = tid & 3;
    cp_async16(s + r * PITCH + c * 16,
               g + (size_t)(row0 + r) * 1024 + k0 + c * 8);
}

template <int MODE>
__global__ void __launch_bounds__(512, 1) mma_gemm(
    const __nv_bfloat16* __restrict__ A_hi, const __nv_bfloat16* __restrict__ A_lo,
    const __nv_bfloat16* __restrict__ B_hi, const __nv_bfloat16* __restrict__ B_lo,
    const float* __restrict__ bias, float* __restrict__ out_f,
    __nv_bfloat16* __restrict__ out_hi, __nv_bfloat16* __restrict__ out_lo,
    int K, float scale) {
    extern __shared__ char smem[];
    const uint32_t sb = smem_u32(smem);
    const int tid = threadIdx.x;
    const int lid = tid & 31;
    const int wid = tid >> 5;
    const int wm = wid >> 2;       // 0..3 -> 32 rows each
    const int wn = wid & 3;        // 0..3 -> 32 cols each
    const int bm = blockIdx.y * 128;
    const int bn = blockIdx.x * 128;

    float acc[2][4][4];
    #pragma unroll
    for (int mt = 0; mt < 2; mt++)
        #pragma unroll
        for (int nt = 0; nt < 4; nt++)
            #pragma unroll
            for (int e = 0; e < 4; e++) acc[mt][nt][e] = 0.0f;

    const int NC = K >> 5;  // BK=32 chunks

    // prologue: stage 0
    load_tile(sb + 0 * TILE_B, A_hi, bm, 0, tid);
    load_tile(sb + 1 * TILE_B, A_lo, bm, 0, tid);
    load_tile(sb + 2 * TILE_B, B_hi, bn, 0, tid);
    load_tile(sb + 3 * TILE_B, B_lo, bn, 0, tid);
    CP_COMMIT();

    // ldmatrix lane addressing (validated in R4)
    const int a_r = lid & 15, a_h = lid >> 4;             // A: rows 0-15, k-half
    const int b_g = lid >> 3, b_r = lid & 7;              // B: group, row
    const int b_nt_add = b_g >> 1, b_kh = b_g & 1;

    for (int c = 0; c < NC; c++) {
        if (c + 1 < NC) {
            const uint32_t st = sb + ((c + 1) & 1) * STAGE_B;
            const int k0 = (c + 1) << 5;
            load_tile(st + 0 * TILE_B, A_hi, bm, k0, tid);
            load_tile(st + 1 * TILE_B, A_lo, bm, k0, tid);
            load_tile(st + 2 * TILE_B, B_hi, bn, k0, tid);
            load_tile(st + 3 * TILE_B, B_lo, bn, k0, tid);
            CP_COMMIT();
            cp_wait<1>();
        } else {
            cp_wait<0>();
        }
        __syncthreads();

        const uint32_t st = sb + (c & 1) * STAGE_B;
        #pragma unroll
        for (int ks = 0; ks < 2; ks++) {
            uint32_t ah[2][4], al[2][4], bh[4][2], bl[4][2];
            #pragma unroll
            for (int mt = 0; mt < 2; mt++) {
                uint32_t ad = st + (uint32_t)((wm * 32 + mt * 16 + a_r) * PITCH
                                              + (ks * 2 + a_h) * 16);
                ldsm_x4(ah[mt], ad);                 // AH tile
                ldsm_x4(al[mt], ad + TILE_B);        // AL tile
            }
            #pragma unroll
            for (int nt = 0; nt < 4; nt += 2) {
                uint32_t bd = st + 2 * TILE_B
                    + (uint32_t)((wn * 32 + (nt + b_nt_add) * 8 + b_r) * PITCH
                                 + (ks * 2 + b_kh) * 16);
                uint32_t t0[4], t1[4];
                ldsm_x4(t0, bd);                     // BH
                ldsm_x4(t1, bd + TILE_B);            // BL
                bh[nt][0] = t0[0]; bh[nt][1] = t0[1];
                bh[nt + 1][0] = t0[2]; bh[nt + 1][1] = t0[3];
                bl[nt][0] = t1[0]; bl[nt][1] = t1[1];
                bl[nt + 1][0] = t1[2]; bl[nt + 1][1] = t1[3];
            }
            #pragma unroll
            for (int mt = 0; mt < 2; mt++)
                #pragma unroll
                for (int nt = 0; nt < 4; nt++) {
                    mma16816(acc[mt][nt], ah[mt], bh[nt]);
                    mma16816(acc[mt][nt], al[mt], bh[nt]);
                    mma16816(acc[mt][nt], ah[mt], bl[nt]);
                }
        }
        __syncthreads();
    }

    // Epilogue: c0,c1 -> (row, col..col+1); c2,c3 -> (row+8, same cols)
    const int er = lid >> 2;           // 0..7
    const int ec = (lid & 3) * 2;      // 0,2,4,6
    #pragma unroll
    for (int mt = 0; mt < 2; mt++) {
        #pragma unroll
        for (int nt = 0; nt < 4; nt++) {
            const int row = bm + wm * 32 + mt * 16 + er;
            const int col = bn + wn * 32 + nt * 8 + ec;
            if (MODE == 0) {
                const float b0 = bias[col], b1 = bias[col + 1];
                float2 v0 = make_float2(acc[mt][nt][0] + b0, acc[mt][nt][1] + b1);
                float2 v1 = make_float2(acc[mt][nt][2] + b0, acc[mt][nt][3] + b1);
                *reinterpret_cast<float2*>(&out_f[(size_t)row * 1024 + col]) = v0;
                *reinterpret_cast<float2*>(&out_f[(size_t)(row + 8) * 1024 + col]) = v1;
            } else {
                #pragma unroll
                for (int half = 0; half < 2; half++) {
                    const float s0 = acc[mt][nt][2 * half + 0] * scale;
                    const float s1 = acc[mt][nt][2 * half + 1] * scale;
                    const __nv_bfloat16 h0 = __float2bfloat16(s0);
                    const __nv_bfloat16 h1 = __float2bfloat16(s1);
                    const size_t o = (size_t)(row + 8 * half) * 1024 + col;
                    *reinterpret_cast<__nv_bfloat162*>(&out_hi[o]) = __nv_bfloat162(h0, h1);
                    *reinterpret_cast<__nv_bfloat162*>(&out_lo[o]) = __nv_bfloat162(
                        __float2bfloat16(s0 - __bfloat162float(h0)),
                        __float2bfloat16(s1 - __bfloat162float(h1)));
                }
            }
        }
    }
}

// ---------------------------------------------------------------------------
extern "C" void kernel_launch(void* const* d_in, const int* in_sizes, int n_in,
                              void* d_out, int out_size) {
    const float* x  = (const float*)d_in[0];
    const float* Wv = (const float*)d_in[6];
    const float* bv = (const float*)d_in[7];
    const float* Wo = (const float*)d_in[8];
    const float* bo = (const float*)d_in[9];
    float* out = (float*)d_out;

    __nv_bfloat16 *x_hi, *x_lo, *wv_hi, *wv_lo, *woT_hi, *woT_lo, *wT_hi, *wT_lo;
    float* beff;
    cudaGetSymbolAddress((void**)&x_hi, g_x_hi);
    cudaGetSymbolAddress((void**)&x_lo, g_x_lo);
    cudaGetSymbolAddress((void**)&wv_hi, g_wv_hi);
    cudaGetSymbolAddress((void**)&wv_lo, g_wv_lo);
    cudaGetSymbolAddress((void**)&woT_hi, g_woT_hi);
    cudaGetSymbolAddress((void**)&woT_lo, g_woT_lo);
    cudaGetSymbolAddress((void**)&wT_hi, g_wT_hi);
    cudaGetSymbolAddress((void**)&wT_lo, g_wT_lo);
    cudaGetSymbolAddress((void**)&beff, g_beff);

    cudaFuncSetAttribute(mma_gemm<0>, cudaFuncAttributeMaxDynamicSharedMemorySize, SMEM_B);
    cudaFuncSetAttribute(mma_gemm<1>, cudaFuncAttributeMaxDynamicSharedMemorySize, SMEM_B);

    // splits: x and Wv plain (row index = their leading dim); Wo transposed.
    split_kernel<<<8192, 256>>>(x, x_hi, x_lo, 8192 * 1024 / 4);
    split_kernel<<<1024, 256>>>(Wv, wv_hi, wv_lo, 1024 * 1024 / 4);
    splitT_kernel<<<dim3(32, 32), dim3(32, 8)>>>(Wo, woT_hi, woT_lo);
    beff_kernel<<<1024, 256>>>(bv, Wo, bo, beff);

    // weffT[n][i] = 2048 * sum_c WoT[n][c] * Wv[i][c]   (epilogue re-splits)
    mma_gemm<1><<<dim3(8, 8), 512, SMEM_B>>>(
        woT_hi, woT_lo, wv_hi, wv_lo, nullptr, nullptr, wT_hi, wT_lo, 1024, 2048.0f);

    // out[m][n] = sum_i x[m][i] * weffT[n][i] + beff[n]
    mma_gemm<0><<<dim3(8, 64), 512, SMEM_B>>>(
        x_hi, x_lo, wT_hi, wT_lo, beff, out, nullptr, nullptr, 1024, 1.0f);
}

// round 9
// speedup vs baseline: 1.0148x; 1.0148x over previous
#include <cuda_runtime.h>
#include <cuda_bf16.h>
#include <cstdint>
#include <cstddef>

// out = x @ (2048 * Wv @ Wo) + (2048 * bv @ Wo + bo)
// (reference's einsum 'bvhd,bhqk->bvhd' sums softmax over q,k -> factor L=2048)
// fp32 emulated as split-bf16: A@B ~= Ah@Bh + Al@Bh + Ah@Bl, fp32 accum,
// via mma.sync.m16n8k16. Loads via cp.async.bulk (1D TMA, base sm_90 ISA) --
// R8 showed the kernel was LDGSTS-issue-bound (32M x 16B cp.async ops).
// BK=64 (128B contiguous rows), PITCH=144 smem (conflict-free ldmatrix, no swizzle).

// ---------------------------------------------------------------------------
__device__ __forceinline__ uint32_t smem_u32(const void* p) {
    uint32_t a;
    asm("{ .reg .u64 t; cvta.to.shared.u64 t, %1; cvt.u32.u64 %0, t; }" : "=r"(a) : "l"(p));
    return a;
}
__device__ __forceinline__ void ldsm_x4(uint32_t* r, uint32_t addr) {
    asm volatile("ldmatrix.sync.aligned.m8n8.x4.shared.b16 {%0,%1,%2,%3}, [%4];"
        : "=r"(r[0]), "=r"(r[1]), "=r"(r[2]), "=r"(r[3]) : "r"(addr));
}
__device__ __forceinline__ void mma16816(float* c, const uint32_t* a, const uint32_t* b) {
    asm volatile(
        "mma.sync.aligned.m16n8k16.row.col.f32.bf16.bf16.f32 "
        "{%0,%1,%2,%3}, {%4,%5,%6,%7}, {%8,%9}, {%0,%1,%2,%3};"
        : "+f"(c[0]), "+f"(c[1]), "+f"(c[2]), "+f"(c[3])
        : "r"(a[0]), "r"(a[1]), "r"(a[2]), "r"(a[3]), "r"(b[0]), "r"(b[1]));
}
#define MBARRIER_INIT(mbar, cnt) \
    asm volatile("mbarrier.init.shared.b64 [%0], %1;" \
        :: "r"((uint32_t)(mbar)), "r"((uint32_t)(cnt)) : "memory")
#define MBARRIER_EXPECT_TX(mbar, bytes) \
    asm volatile("mbarrier.arrive.expect_tx.shared.b64 _, [%0], %1;" \
        :: "r"((uint32_t)(mbar)), "r"((uint32_t)(bytes)) : "memory")
#define MBARRIER_WAIT_PARITY(mbar, parity) do { \
    uint32_t _m = (uint32_t)(mbar); uint32_t _p = (uint32_t)(parity); uint32_t _d; \
    asm volatile("{\n\t.reg .pred p;\n\t" \
        "mbarrier.try_wait.parity.acquire.cta.shared::cta.b64 p, [%1], %2;\n\t" \
        "selp.b32 %0, 1, 0, p;\n\t}" : "=r"(_d) : "r"(_m), "r"(_p) : "memory"); \
    if (!_d) { \
        asm volatile("{\n\t.reg .pred P1;\n\t" \
            "WL_%=:\n\t" \
            "mbarrier.try_wait.parity.acquire.cta.shared::cta.b64 P1, [%0], %1, 0x989680;\n\t" \
            "@P1 bra.uni WD_%=;\n\t" \
            "bra.uni WL_%=;\n\t" \
            "WD_%=:\n\t}" :: "r"(_m), "r"(_p) : "memory"); \
    } \
} while (0)
__device__ __forceinline__ void bulk_g2s_128(uint32_t dst, const void* src, uint32_t mbar) {
    asm volatile(
        "cp.async.bulk.shared::cta.global.mbarrier::complete_tx::bytes [%0], [%1], 128, [%2];"
        :: "r"(dst), "l"(src), "r"(mbar) : "memory");
}

// ---------------------------------------------------------------------------
// Scratch (__device__ globals; no allocation allowed)
// ---------------------------------------------------------------------------
__device__ __nv_bfloat16 g_x_hi[8192 * 1024];
__device__ __nv_bfloat16 g_x_lo[8192 * 1024];
__device__ __nv_bfloat16 g_wv_hi[1024 * 1024];
__device__ __nv_bfloat16 g_wv_lo[1024 * 1024];
__device__ __nv_bfloat16 g_woT_hi[1024 * 1024];
__device__ __nv_bfloat16 g_woT_lo[1024 * 1024];
__device__ __nv_bfloat16 g_wT_hi[1024 * 1024];
__device__ __nv_bfloat16 g_wT_lo[1024 * 1024];
__device__ float g_beff[1024];

// ---------------------------------------------------------------------------
// Conversion kernels
// ---------------------------------------------------------------------------
__global__ void split_kernel(const float* __restrict__ in,
                             __nv_bfloat16* __restrict__ hi,
                             __nv_bfloat16* __restrict__ lo, int n4) {
    int i = blockIdx.x * blockDim.x + threadIdx.x;
    if (i >= n4) return;
    float4 v = reinterpret_cast<const float4*>(in)[i];
    __nv_bfloat16 h0 = __float2bfloat16(v.x), h1 = __float2bfloat16(v.y);
    __nv_bfloat16 h2 = __float2bfloat16(v.z), h3 = __float2bfloat16(v.w);
    __nv_bfloat162* hp = reinterpret_cast<__nv_bfloat162*>(hi);
    __nv_bfloat162* lp = reinterpret_cast<__nv_bfloat162*>(lo);
    hp[2 * i]     = __nv_bfloat162(h0, h1);
    hp[2 * i + 1] = __nv_bfloat162(h2, h3);
    lp[2 * i]     = __nv_bfloat162(__float2bfloat16(v.x - __bfloat162float(h0)),
                                   __float2bfloat16(v.y - __bfloat162float(h1)));
    lp[2 * i + 1] = __nv_bfloat162(__float2bfloat16(v.z - __bfloat162float(h2)),
                                   __float2bfloat16(v.w - __bfloat162float(h3)));
}

// Transposing split: out[n][c] = split(in[c][n]); 1024x1024
__global__ void splitT_kernel(const float* __restrict__ in,
                              __nv_bfloat16* __restrict__ hiT,
                              __nv_bfloat16* __restrict__ loT) {
    __shared__ float t[32][33];
    const int bx = blockIdx.x * 32, by = blockIdx.y * 32;
    const int tx = threadIdx.x, ty = threadIdx.y;  // 32 x 8
    #pragma unroll
    for (int i = 0; i < 32; i += 8)
        t[ty + i][tx] = in[(size_t)(by + ty + i) * 1024 + bx + tx];
    __syncthreads();
    #pragma unroll
    for (int i = 0; i < 32; i += 8) {
        float v = t[tx][ty + i];
        __nv_bfloat16 h = __float2bfloat16(v);
        size_t o = (size_t)(bx + ty + i) * 1024 + by + tx;
        hiT[o] = h;
        loT[o] = __float2bfloat16(v - __bfloat162float(h));
    }
}

// beff[j] = 2048 * sum_k bv[k]*Wo[k][j] + bo[j]; one block per j
__global__ void beff_kernel(const float* __restrict__ bv, const float* __restrict__ Wo,
                            const float* __restrict__ bo, float* __restrict__ beff) {
    __shared__ float red[256];
    const int j = blockIdx.x;
    float s = 0.0f;
    for (int k = threadIdx.x; k < 1024; k += 256)
        s += bv[k] * Wo[(size_t)k * 1024 + j];
    red[threadIdx.x] = s;
    __syncthreads();
    for (int st = 128; st > 0; st >>= 1) {
        if (threadIdx.x < st) red[threadIdx.x] += red[threadIdx.x + st];
        __syncthreads();
    }
    if (threadIdx.x == 0) beff[j] = 2048.0f * red[0] + bo[j];
}

// ---------------------------------------------------------------------------
// Split-bf16 GEMM via mma.sync + cp.async.bulk: D[m][n] = sum_k A[m][k]*B[n][k]
//   A: [M x 1024] K-major (hi/lo), B: [N x 1024] K-major (hi/lo)
// MODE 0: out_f = D + bias;  MODE 1: (out_hi,out_lo) = split(D * scale)
// CTA tile 128x128, BK=64, 512 thr (16 warps, 4x4), warp tile 32x32,
// double-buffered bulk-copy (1 x 128B row per thread), PITCH-144 smem.
// ---------------------------------------------------------------------------
#define PITCH 144
#define TILE_B (128 * PITCH)       // 18432 bytes: one 128x64 bf16 tile (padded)
#define STAGE_B (4 * TILE_B)       // AH, AL, BH, BL = 73728
#define BAR_OFF (2 * STAGE_B)      // 147456
#define SMEM_B (BAR_OFF + 16)      // two mbarriers

template <int MODE>
__global__ void __launch_bounds__(512, 1) mma_gemm(
    const __nv_bfloat16* __restrict__ A_hi, const __nv_bfloat16* __restrict__ A_lo,
    const __nv_bfloat16* __restrict__ B_hi, const __nv_bfloat16* __restrict__ B_lo,
    const float* __restrict__ bias, float* __restrict__ out_f,
    __nv_bfloat16* __restrict__ out_hi, __nv_bfloat16* __restrict__ out_lo,
    int K, float scale) {
    extern __shared__ char smem[];
    const uint32_t sb = smem_u32(smem);
    const int tid = threadIdx.x;
    const int lid = tid & 31;
    const int wid = tid >> 5;
    const int wm = wid >> 2;       // 0..3 -> 32 rows each
    const int wn = wid & 3;        // 0..3 -> 32 cols each
    const int bm = blockIdx.y * 128;
    const int bn = blockIdx.x * 128;

    // bulk-load mapping: tile = tid>>7 (AH,AL,BH,BL), row = tid&127
    const int ld_tile = tid >> 7;
    const int ld_row = tid & 127;
    const __nv_bfloat16* ld_base =
        (ld_tile == 0) ? A_hi : (ld_tile == 1) ? A_lo : (ld_tile == 2) ? B_hi : B_lo;
    const int ld_r0 = (ld_tile < 2) ? bm : bn;
    const __nv_bfloat16* ld_src_row = ld_base + (size_t)(ld_r0 + ld_row) * 1024;
    const uint32_t ld_dst = sb + ld_tile * TILE_B + ld_row * PITCH;

    if (tid == 0) {
        MBARRIER_INIT(sb + BAR_OFF, 1);
        MBARRIER_INIT(sb + BAR_OFF + 8, 1);
    }
    __syncthreads();

    float acc[2][4][4];
    #pragma unroll
    for (int mt = 0; mt < 2; mt++)
        #pragma unroll
        for (int nt = 0; nt < 4; nt++)
            #pragma unroll
            for (int e = 0; e < 4; e++) acc[mt][nt][e] = 0.0f;

    const int NC = K >> 6;  // BK=64 chunks
    int ph0 = 0, ph1 = 0;

    // prologue: chunk 0 -> stage 0  (expect 4 tiles x 16KB payload = 64KB)
    if (tid == 0) MBARRIER_EXPECT_TX(sb + BAR_OFF, 65536);
    bulk_g2s_128(ld_dst, ld_src_row, sb + BAR_OFF);

    // ldmatrix lane addressing (validated in R4)
    const int a_r = lid & 15, a_h = lid >> 4;             // A: rows 0-15, k-half
    const int b_g = lid >> 3, b_r = lid & 7;              // B: group, row
    const int b_nt_add = b_g >> 1, b_kh = b_g & 1;

    for (int c = 0; c < NC; c++) {
        const int s = c & 1;
        if (c + 1 < NC) {
            // refill the other stage (its consumers finished at end of chunk c-1)
            const int s2 = (c + 1) & 1;
            const uint32_t bar2 = sb + BAR_OFF + s2 * 8;
            if (tid == 0) MBARRIER_EXPECT_TX(bar2, 65536);
            bulk_g2s_128(ld_dst + s2 * STAGE_B, ld_src_row + ((c + 1) << 6), bar2);
        }
        // wait for stage s
        if (s == 0) { MBARRIER_WAIT_PARITY(sb + BAR_OFF, ph0); ph0 ^= 1; }
        else        { MBARRIER_WAIT_PARITY(sb + BAR_OFF + 8, ph1); ph1 ^= 1; }

        const uint32_t st = sb + s * STAGE_B;
        #pragma unroll
        for (int ks = 0; ks < 4; ks++) {
            uint32_t ah[2][4], al[2][4], bh[4][2], bl[4][2];
            #pragma unroll
            for (int mt = 0; mt < 2; mt++) {
                uint32_t ad = st + (uint32_t)((wm * 32 + mt * 16 + a_r) * PITCH
                                              + (ks * 2 + a_h) * 16);
                ldsm_x4(ah[mt], ad);                 // AH tile
                ldsm_x4(al[mt], ad + TILE_B);        // AL tile
            }
            #pragma unroll
            for (int nt = 0; nt < 4; nt += 2) {
                uint32_t bd = st + 2 * TILE_B
                    + (uint32_t)((wn * 32 + (nt + b_nt_add) * 8 + b_r) * PITCH
                                 + (ks * 2 + b_kh) * 16);
                uint32_t t0[4], t1[4];
                ldsm_x4(t0, bd);                     // BH
                ldsm_x4(t1, bd + TILE_B);            // BL
                bh[nt][0] = t0[0]; bh[nt][1] = t0[1];
                bh[nt + 1][0] = t0[2]; bh[nt + 1][1] = t0[3];
                bl[nt][0] = t1[0]; bl[nt][1] = t1[1];
                bl[nt + 1][0] = t1[2]; bl[nt + 1][1] = t1[3];
            }
            #pragma unroll
            for (int mt = 0; mt < 2; mt++)
                #pragma unroll
                for (int nt = 0; nt < 4; nt++) {
                    mma16816(acc[mt][nt], ah[mt], bh[nt]);
                    mma16816(acc[mt][nt], al[mt], bh[nt]);
                    mma16816(acc[mt][nt], ah[mt], bl[nt]);
                }
        }
        __syncthreads();   // all consumers done with stage s before it is refilled
    }

    // Epilogue: c0,c1 -> (row, col..col+1); c2,c3 -> (row+8, same cols)
    const int er = lid >> 2;           // 0..7
    const int ec = (lid & 3) * 2;      // 0,2,4,6
    #pragma unroll
    for (int mt = 0; mt < 2; mt++) {
        #pragma unroll
        for (int nt = 0; nt < 4; nt++) {
            const int row = bm + wm * 32 + mt * 16 + er;
            const int col = bn + wn * 32 + nt * 8 + ec;
            if (MODE == 0) {
                const float b0 = bias[col], b1 = bias[col + 1];
                float2 v0 = make_float2(acc[mt][nt][0] + b0, acc[mt][nt][1] + b1);
                float2 v1 = make_float2(acc[mt][nt][2] + b0, acc[mt][nt][3] + b1);
                *reinterpret_cast<float2*>(&out_f[(size_t)row * 1024 + col]) = v0;
                *reinterpret_cast<float2*>(&out_f[(size_t)(row + 8) * 1024 + col]) = v1;
            } else {
                #pragma unroll
                for (int half = 0; half < 2; half++) {
                    const float s0 = acc[mt][nt][2 * half + 0] * scale;
                    const float s1 = acc[mt][nt][2 * half + 1] * scale;
                    const __nv_bfloat16 h0 = __float2bfloat16(s0);
                    const __nv_bfloat16 h1 = __float2bfloat16(s1);
                    const size_t o = (size_t)(row + 8 * half) * 1024 + col;
                    *reinterpret_cast<__nv_bfloat162*>(&out_hi[o]) = __nv_bfloat162(h0, h1);
                    *reinterpret_cast<__nv_bfloat162*>(&out_lo[o]) = __nv_bfloat162(
                        __float2bfloat16(s0 - __bfloat162float(h0)),
                        __float2bfloat16(s1 - __bfloat162float(h1)));
                }
            }
        }
    }
}

// ---------------------------------------------------------------------------
extern "C" void kernel_launch(void* const* d_in, const int* in_sizes, int n_in,
                              void* d_out, int out_size) {
    const float* x  = (const float*)d_in[0];
    const float* Wv = (const float*)d_in[6];
    const float* bv = (const float*)d_in[7];
    const float* Wo = (const float*)d_in[8];
    const float* bo = (const float*)d_in[9];
    float* out = (float*)d_out;

    __nv_bfloat16 *x_hi, *x_lo, *wv_hi, *wv_lo, *woT_hi, *woT_lo, *wT_hi, *wT_lo;
    float* beff;
    cudaGetSymbolAddress((void**)&x_hi, g_x_hi);
    cudaGetSymbolAddress((void**)&x_lo, g_x_lo);
    cudaGetSymbolAddress((void**)&wv_hi, g_wv_hi);
    cudaGetSymbolAddress((void**)&wv_lo, g_wv_lo);
    cudaGetSymbolAddress((void**)&woT_hi, g_woT_hi);
    cudaGetSymbolAddress((void**)&woT_lo, g_woT_lo);
    cudaGetSymbolAddress((void**)&wT_hi, g_wT_hi);
    cudaGetSymbolAddress((void**)&wT_lo, g_wT_lo);
    cudaGetSymbolAddress((void**)&beff, g_beff);

    cudaFuncSetAttribute(mma_gemm<0>, cudaFuncAttributeMaxDynamicSharedMemorySize, SMEM_B);
    cudaFuncSetAttribute(mma_gemm<1>, cudaFuncAttributeMaxDynamicSharedMemorySize, SMEM_B);

    // splits: x and Wv plain (row index = their leading dim); Wo transposed.
    split_kernel<<<8192, 256>>>(x, x_hi, x_lo, 8192 * 1024 / 4);
    split_kernel<<<1024, 256>>>(Wv, wv_hi, wv_lo, 1024 * 1024 / 4);
    splitT_kernel<<<dim3(32, 32), dim3(32, 8)>>>(Wo, woT_hi, woT_lo);
    beff_kernel<<<1024, 256>>>(bv, Wo, bo, beff);

    // weffT[n][i] = 2048 * sum_c WoT[n][c] * Wv[i][c]   (epilogue re-splits)
    mma_gemm<1><<<dim3(8, 8), 512, SMEM_B>>>(
        woT_hi, woT_lo, wv_hi, wv_lo, nullptr, nullptr, wT_hi, wT_lo, 1024, 2048.0f);

    // out[m][n] = sum_i x[m][i] * weffT[n][i] + beff[n]
    mma_gemm<0><<<dim3(8, 64), 512, SMEM_B>>>(
        x_hi, x_lo, wT_hi, wT_lo, beff, out, nullptr, nullptr, 1024, 1.0f);
}